// round 12
// baseline (speedup 1.0000x reference)
#include <cuda_runtime.h>
#include <cstdint>

// ---------------------------------------------------------------------------
// CollectAtomTriples: idx_i SORTED int32 [n], values in [0, VMAX). For each
// run (segment) s of equal values (size c, start off) emit all C(c,2) pairs
// (a<b, combinations order), PLANAR FLOAT32 output (values < 2^24: exact):
//   out[0:T)=s   out[T:2T)=off+a   out[2T:3T)=off+b
// ---------------------------------------------------------------------------

#define VMAX   65536
#define NCHUNK 256
#define CHUNK  256              // VMAX / NCHUNK
#define EMIT_PER_THREAD 8
#define EMIT_BLOCK 256
#define TRIPLES_PER_BLOCK (EMIT_PER_THREAD * EMIT_BLOCK)   // 2048

__device__ int d_pos[VMAX + 1];       // pos[v] = lower_bound(idx, v)
__device__ int d_triOffV[VMAX + 1];   // exclusive prefix of C(cnt(v),2); [VMAX]=T
__device__ int d_segIdV[VMAX];        // exclusive prefix of present-flag
__device__ int d_chunkTri[NCHUNK];
__device__ int d_chunkFlag[NCHUNK];
__device__ int d_chunkTriOff[NCHUNK];
__device__ int d_chunkFlagOff[NCHUNK];

// ---------------- K1: pos[v] = lower_bound(idx, n, v) ----------------------
__global__ void k_pos(const int* __restrict__ idx, int n) {
    int v = blockIdx.x * blockDim.x + threadIdx.x;
    if (v > VMAX) return;
    int lo = 0, hi = n;
    while (lo < hi) {
        int m = (lo + hi) >> 1;
        if (__ldg(&idx[m]) < v) lo = m + 1; else hi = m;
    }
    d_pos[v] = lo;
}

__device__ __forceinline__ long long pack2(int fl, int tri) {
    return ((long long)fl << 32) | (unsigned int)tri;
}

// block-wide inclusive scan of packed 64-bit values (blockDim.x = 256)
__device__ __forceinline__ long long block_scan_ll(long long v) {
    const int lane = threadIdx.x & 31;
    const int warp = threadIdx.x >> 5;
    #pragma unroll
    for (int o = 1; o < 32; o <<= 1) {
        long long u = __shfl_up_sync(0xffffffffu, v, o);
        if (lane >= o) v += u;
    }
    __shared__ long long wsum[8];
    if (lane == 31) wsum[warp] = v;
    __syncthreads();
    if (warp == 0) {
        long long w = (lane < 8) ? wsum[lane] : 0;
        #pragma unroll
        for (int o = 1; o < 8; o <<= 1) {
            long long u = __shfl_up_sync(0xffffffffu, w, o);
            if (lane >= o) w += u;
        }
        if (lane < 8) wsum[lane] = w;
    }
    __syncthreads();
    long long add = (warp > 0) ? wsum[warp - 1] : 0;
    return v + add;
}

// ---------------- K2: per-chunk totals -------------------------------------
__global__ void k_sum() {
    int v = blockIdx.x * CHUNK + threadIdx.x;
    int cnt = d_pos[v + 1] - d_pos[v];
    long long p = pack2(cnt > 0, cnt * (cnt - 1) / 2);
    const int lane = threadIdx.x & 31;
    const int warp = threadIdx.x >> 5;
    #pragma unroll
    for (int o = 16; o > 0; o >>= 1)
        p += __shfl_down_sync(0xffffffffu, p, o);
    __shared__ long long ws[8];
    if (lane == 0) ws[warp] = p;
    __syncthreads();
    if (threadIdx.x == 0) {
        long long s = 0;
        #pragma unroll
        for (int w = 0; w < 8; w++) s += ws[w];
        d_chunkTri[blockIdx.x]  = (int)(s & 0xffffffffLL);
        d_chunkFlag[blockIdx.x] = (int)(s >> 32);
    }
}

// ---------------- K3: scan the 256 chunk totals ----------------------------
__global__ void k_scan256() {
    int i = threadIdx.x;
    long long p = pack2(d_chunkFlag[i], d_chunkTri[i]);
    long long incl = block_scan_ll(p);
    long long excl = incl - p;
    d_chunkTriOff[i]  = (int)(excl & 0xffffffffLL);
    d_chunkFlagOff[i] = (int)(excl >> 32);
    if (i == NCHUNK - 1)
        d_triOffV[VMAX] = (int)(incl & 0xffffffffLL);   // sentinel = T
}

// ---------------- K4: per-value prefixes -----------------------------------
__global__ void k_fill() {
    int v = blockIdx.x * CHUNK + threadIdx.x;
    int cnt = d_pos[v + 1] - d_pos[v];
    long long p = pack2(cnt > 0, cnt * (cnt - 1) / 2);
    long long incl = block_scan_ll(p);
    long long excl = incl - p;
    d_triOffV[v] = d_chunkTriOff[blockIdx.x]  + (int)(excl & 0xffffffffLL);
    d_segIdV[v]  = d_chunkFlagOff[blockIdx.x] + (int)(excl >> 32);
}

// full-range owner search: largest v in [0, VMAX-1] with triOffV[v] <= t
__device__ __forceinline__ int owner_full(int t) {
    int lo = 0, hi = VMAX - 1;
    #pragma unroll
    for (int step = 0; step < 16; step++) {
        int mid = (lo + hi + 1) >> 1;
        if (__ldg(&d_triOffV[mid]) <= t) lo = mid; else hi = mid - 1;
    }
    return lo;
}

// ---------------- K5: emit, block-coarse search + 8 triples/thread ---------
__global__ void k_emit(float* __restrict__ out, int T) {
    __shared__ int s_vlo, s_vhi;
    int blockStart = blockIdx.x * TRIPLES_PER_BLOCK;
    int blockLast  = blockStart + TRIPLES_PER_BLOCK - 1;
    if (blockLast >= T) blockLast = T - 1;

    if (threadIdx.x == 0)  s_vlo = owner_full(blockStart);
    if (threadIdx.x == 32) s_vhi = owner_full(blockLast);
    __syncthreads();

    int t0 = blockStart + threadIdx.x * EMIT_PER_THREAD;
    if (t0 >= T) return;

    // narrowed owner search (range typically a handful of values, L1/L2-hot)
    int lo = s_vlo, hi = s_vhi;
    while (lo < hi) {
        int mid = (lo + hi + 1) >> 1;
        if (__ldg(&d_triOffV[mid]) <= t0) lo = mid; else hi = mid - 1;
    }
    int v       = lo;
    int off     = __ldg(&d_triOffV[v]);
    int nextOff = __ldg(&d_triOffV[v + 1]);
    int beg     = __ldg(&d_pos[v]);
    int c       = __ldg(&d_pos[v + 1]) - beg;
    int s       = __ldg(&d_segIdV[v]);
    int M       = c * (c - 1) / 2;

    #pragma unroll
    for (int k = 0; k < EMIT_PER_THREAD; k++) {
        int t = t0 + k;
        if (t >= T) break;
        while (t >= nextOff) {          // advance owner (skips empty values)
            v++;
            off = nextOff;
            nextOff = __ldg(&d_triOffV[v + 1]);
            beg = __ldg(&d_pos[v]);
            c   = __ldg(&d_pos[v + 1]) - beg;
            s   = __ldg(&d_segIdV[v]);
            M   = c * (c - 1) / 2;
        }
        int r  = t - off;
        int rr = M - 1 - r;
        int a_rev = (int)floorf((sqrtf(8.0f * (float)rr + 1.0f) - 1.0f) * 0.5f);
        if (a_rev < 0) a_rev = 0;
        if ((a_rev + 1) * (a_rev + 2) / 2 <= rr) a_rev++;
        if (a_rev * (a_rev + 1) / 2 > rr)        a_rev--;
        int a = c - 2 - a_rev;
        int b = c - 1 - (rr - a_rev * (a_rev + 1) / 2);

        __stcs(&out[t],         (float)s);          // streaming: never re-read
        __stcs(&out[T + t],     (float)(beg + a));
        __stcs(&out[2 * T + t], (float)(beg + b));
    }
}

// ---------------------------------------------------------------------------
extern "C" void kernel_launch(void* const* d_in, const int* in_sizes, int n_in,
                              void* d_out, int out_size) {
    const int* idx = (const int*)d_in[0];
    int n = in_sizes[0];
    int T = out_size / 3;                 // planar [s | j | k], float32
    float* out = (float*)d_out;

    k_pos<<<(VMAX + 1 + 255) / 256, 256>>>(idx, n);
    k_sum<<<NCHUNK, CHUNK>>>();
    k_scan256<<<1, NCHUNK>>>();
    k_fill<<<NCHUNK, CHUNK>>>();
    int nblk = (T + TRIPLES_PER_BLOCK - 1) / TRIPLES_PER_BLOCK;
    k_emit<<<nblk, EMIT_BLOCK>>>(out, T);
}

// round 13
// speedup vs baseline: 3.2857x; 3.2857x over previous
#include <cuda_runtime.h>
#include <cstdint>

// ---------------------------------------------------------------------------
// CollectAtomTriples: idx_i SORTED int32 [n], values in [0, VMAX). For each
// run (segment) s of equal values (size c, start off) emit all C(c,2) pairs
// (a<b, combinations order), PLANAR FLOAT32 output (values < 2^24: exact):
//   out[0:T)=s   out[T:2T)=off+a   out[2T:3T)=off+b
// ---------------------------------------------------------------------------

#define VMAX   65536
#define NCHUNK 256
#define CHUNK  256              // VMAX / NCHUNK
#define EMIT_PER_THREAD 8
#define EMIT_BLOCK 256
#define TRIPLES_PER_BLOCK (EMIT_PER_THREAD * EMIT_BLOCK)   // 2048

__device__ int d_pos[VMAX + 1];       // pos[v] = lower_bound(idx, v)
__device__ int d_triOffV[VMAX + 1];   // exclusive prefix of C(cnt(v),2); [VMAX]=T
__device__ int d_segIdV[VMAX];        // exclusive prefix of present-flag
__device__ int d_chunkTri[NCHUNK];
__device__ int d_chunkFlag[NCHUNK];
__device__ int d_chunkTriOff[NCHUNK];
__device__ int d_chunkFlagOff[NCHUNK];

// ---------------- K1: pos[v] = lower_bound(idx, n, v) ----------------------
__global__ void k_pos(const int* __restrict__ idx, int n) {
    int v = blockIdx.x * blockDim.x + threadIdx.x;
    if (v > VMAX) return;
    int lo = 0, hi = n;
    while (lo < hi) {
        int m = (lo + hi) >> 1;
        if (__ldg(&idx[m]) < v) lo = m + 1; else hi = m;
    }
    d_pos[v] = lo;
}

__device__ __forceinline__ long long pack2(int fl, int tri) {
    return ((long long)fl << 32) | (unsigned int)tri;
}

// block-wide inclusive scan of packed 64-bit values (blockDim.x = 256)
__device__ __forceinline__ long long block_scan_ll(long long v) {
    const int lane = threadIdx.x & 31;
    const int warp = threadIdx.x >> 5;
    #pragma unroll
    for (int o = 1; o < 32; o <<= 1) {
        long long u = __shfl_up_sync(0xffffffffu, v, o);
        if (lane >= o) v += u;
    }
    __shared__ long long wsum[8];
    if (lane == 31) wsum[warp] = v;
    __syncthreads();
    if (warp == 0) {
        long long w = (lane < 8) ? wsum[lane] : 0;
        #pragma unroll
        for (int o = 1; o < 8; o <<= 1) {
            long long u = __shfl_up_sync(0xffffffffu, w, o);
            if (lane >= o) w += u;
        }
        if (lane < 8) wsum[lane] = w;
    }
    __syncthreads();
    long long add = (warp > 0) ? wsum[warp - 1] : 0;
    return v + add;
}

// ---------------- K2: per-chunk totals -------------------------------------
__global__ void k_sum() {
    int v = blockIdx.x * CHUNK + threadIdx.x;
    int cnt = d_pos[v + 1] - d_pos[v];
    long long p = pack2(cnt > 0, cnt * (cnt - 1) / 2);
    const int lane = threadIdx.x & 31;
    const int warp = threadIdx.x >> 5;
    #pragma unroll
    for (int o = 16; o > 0; o >>= 1)
        p += __shfl_down_sync(0xffffffffu, p, o);
    __shared__ long long ws[8];
    if (lane == 0) ws[warp] = p;
    __syncthreads();
    if (threadIdx.x == 0) {
        long long s = 0;
        #pragma unroll
        for (int w = 0; w < 8; w++) s += ws[w];
        d_chunkTri[blockIdx.x]  = (int)(s & 0xffffffffLL);
        d_chunkFlag[blockIdx.x] = (int)(s >> 32);
    }
}

// ---------------- K3: scan the 256 chunk totals ----------------------------
__global__ void k_scan256() {
    int i = threadIdx.x;
    long long p = pack2(d_chunkFlag[i], d_chunkTri[i]);
    long long incl = block_scan_ll(p);
    long long excl = incl - p;
    d_chunkTriOff[i]  = (int)(excl & 0xffffffffLL);
    d_chunkFlagOff[i] = (int)(excl >> 32);
    if (i == NCHUNK - 1)
        d_triOffV[VMAX] = (int)(incl & 0xffffffffLL);   // sentinel = T
}

// ---------------- K4: per-value prefixes -----------------------------------
__global__ void k_fill() {
    int v = blockIdx.x * CHUNK + threadIdx.x;
    int cnt = d_pos[v + 1] - d_pos[v];
    long long p = pack2(cnt > 0, cnt * (cnt - 1) / 2);
    long long incl = block_scan_ll(p);
    long long excl = incl - p;
    d_triOffV[v] = d_chunkTriOff[blockIdx.x]  + (int)(excl & 0xffffffffLL);
    d_segIdV[v]  = d_chunkFlagOff[blockIdx.x] + (int)(excl >> 32);
}

// full-range owner search: largest v in [0, VMAX-1] with triOffV[v] <= t
__device__ __forceinline__ int owner_full(int t) {
    int lo = 0, hi = VMAX - 1;
    #pragma unroll
    for (int step = 0; step < 16; step++) {
        int mid = (lo + hi + 1) >> 1;
        if (__ldg(&d_triOffV[mid]) <= t) lo = mid; else hi = mid - 1;
    }
    return lo;
}

// ---------------- K5: emit — coalesced mapping, coarse search --------------
// Thread tid handles t = blockStart + k*EMIT_BLOCK + tid, k = 0..7: every
// warp store writes 32 consecutive floats (one full 128B line) in each of
// the three planar streams. Owner state walks forward across iterations.
__global__ void k_emit(float* __restrict__ out, int T) {
    __shared__ int s_vlo, s_vhi;
    int blockStart = blockIdx.x * TRIPLES_PER_BLOCK;
    int blockLast  = blockStart + TRIPLES_PER_BLOCK - 1;
    if (blockLast >= T) blockLast = T - 1;

    if (threadIdx.x == 0)  s_vlo = owner_full(blockStart);
    if (threadIdx.x == 32) s_vhi = owner_full(blockLast);
    __syncthreads();

    int t0 = blockStart + threadIdx.x;
    if (t0 >= T) return;

    // narrowed owner search for the first t (range is a handful of values)
    int lo = s_vlo, hi = s_vhi;
    while (lo < hi) {
        int mid = (lo + hi + 1) >> 1;
        if (__ldg(&d_triOffV[mid]) <= t0) lo = mid; else hi = mid - 1;
    }
    int v       = lo;
    int off     = __ldg(&d_triOffV[v]);
    int nextOff = __ldg(&d_triOffV[v + 1]);
    int beg     = __ldg(&d_pos[v]);
    int c       = __ldg(&d_pos[v + 1]) - beg;
    int s       = __ldg(&d_segIdV[v]);
    int M       = c * (c - 1) / 2;

    #pragma unroll
    for (int k = 0; k < EMIT_PER_THREAD; k++) {
        int t = t0 + k * EMIT_BLOCK;
        if (t >= T) break;
        while (t >= nextOff) {          // advance owner (skips empty values)
            v++;
            off = nextOff;
            nextOff = __ldg(&d_triOffV[v + 1]);
            beg = __ldg(&d_pos[v]);
            c   = __ldg(&d_pos[v + 1]) - beg;
            s   = __ldg(&d_segIdV[v]);
            M   = c * (c - 1) / 2;
        }
        int r  = t - off;
        int rr = M - 1 - r;
        int a_rev = (int)floorf((sqrtf(8.0f * (float)rr + 1.0f) - 1.0f) * 0.5f);
        if (a_rev < 0) a_rev = 0;
        if ((a_rev + 1) * (a_rev + 2) / 2 <= rr) a_rev++;
        if (a_rev * (a_rev + 1) / 2 > rr)        a_rev--;
        int a = c - 2 - a_rev;
        int b = c - 1 - (rr - a_rev * (a_rev + 1) / 2);

        out[t]         = (float)s;        // fully coalesced: default caching
        out[T + t]     = (float)(beg + a);
        out[2 * T + t] = (float)(beg + b);
    }
}

// ---------------------------------------------------------------------------
extern "C" void kernel_launch(void* const* d_in, const int* in_sizes, int n_in,
                              void* d_out, int out_size) {
    const int* idx = (const int*)d_in[0];
    int n = in_sizes[0];
    int T = out_size / 3;                 // planar [s | j | k], float32
    float* out = (float*)d_out;

    k_pos<<<(VMAX + 1 + 255) / 256, 256>>>(idx, n);
    k_sum<<<NCHUNK, CHUNK>>>();
    k_scan256<<<1, NCHUNK>>>();
    k_fill<<<NCHUNK, CHUNK>>>();
    int nblk = (T + TRIPLES_PER_BLOCK - 1) / TRIPLES_PER_BLOCK;
    k_emit<<<nblk, EMIT_BLOCK>>>(out, T);
}

// round 14
// speedup vs baseline: 3.7442x; 1.1395x over previous
#include <cuda_runtime.h>
#include <cstdint>

// ---------------------------------------------------------------------------
// CollectAtomTriples: idx_i SORTED int32 [n], values in [0, VMAX). For each
// run (segment) s of equal values (size c, start off) emit all C(c,2) pairs
// (a<b, combinations order), PLANAR FLOAT32 output (values < 2^24: exact):
//   out[0:T)=s   out[T:2T)=off+a   out[2T:3T)=off+b
// ---------------------------------------------------------------------------

#define VMAX   65536
#define NCHUNK 256
#define CHUNK  256              // VMAX / NCHUNK
#define EMIT_PER_THREAD 16
#define EMIT_BLOCK 256
#define TRIPLES_PER_BLOCK (EMIT_PER_THREAD * EMIT_BLOCK)   // 4096

__device__ int d_pos[VMAX + 1];       // pos[v] = lower_bound(idx, v)
__device__ int d_triOffV[VMAX + 1];   // exclusive prefix of C(cnt(v),2); [VMAX]=T
__device__ int d_segIdV[VMAX];        // exclusive prefix of present-flag
__device__ int d_chunkTri[NCHUNK];
__device__ int d_chunkFlag[NCHUNK];

// ---------------- K1: pos[v] = lower_bound(idx, n, v) ----------------------
__global__ void k_pos(const int* __restrict__ idx, int n) {
    int v = blockIdx.x * blockDim.x + threadIdx.x;
    if (v > VMAX) return;
    int lo = 0, hi = n;
    while (lo < hi) {
        int m = (lo + hi) >> 1;
        if (__ldg(&idx[m]) < v) lo = m + 1; else hi = m;
    }
    d_pos[v] = lo;
}

__device__ __forceinline__ long long pack2(int fl, int tri) {
    return ((long long)fl << 32) | (unsigned int)tri;
}

// block-wide inclusive scan of packed 64-bit values (blockDim.x = 256)
__device__ __forceinline__ long long block_scan_ll(long long v) {
    const int lane = threadIdx.x & 31;
    const int warp = threadIdx.x >> 5;
    #pragma unroll
    for (int o = 1; o < 32; o <<= 1) {
        long long u = __shfl_up_sync(0xffffffffu, v, o);
        if (lane >= o) v += u;
    }
    __shared__ long long wsum[8];
    if (lane == 31) wsum[warp] = v;
    __syncthreads();
    if (warp == 0) {
        long long w = (lane < 8) ? wsum[lane] : 0;
        #pragma unroll
        for (int o = 1; o < 8; o <<= 1) {
            long long u = __shfl_up_sync(0xffffffffu, w, o);
            if (lane >= o) w += u;
        }
        if (lane < 8) wsum[lane] = w;
    }
    __syncthreads();
    long long add = (warp > 0) ? wsum[warp - 1] : 0;
    return v + add;
}

// ---------------- K2: per-chunk totals -------------------------------------
__global__ void k_sum() {
    int v = blockIdx.x * CHUNK + threadIdx.x;
    int cnt = d_pos[v + 1] - d_pos[v];
    long long p = pack2(cnt > 0, cnt * (cnt - 1) / 2);
    const int lane = threadIdx.x & 31;
    const int warp = threadIdx.x >> 5;
    #pragma unroll
    for (int o = 16; o > 0; o >>= 1)
        p += __shfl_down_sync(0xffffffffu, p, o);
    __shared__ long long ws[8];
    if (lane == 0) ws[warp] = p;
    __syncthreads();
    if (threadIdx.x == 0) {
        long long s = 0;
        #pragma unroll
        for (int w = 0; w < 8; w++) s += ws[w];
        d_chunkTri[blockIdx.x]  = (int)(s & 0xffffffffLL);
        d_chunkFlag[blockIdx.x] = (int)(s >> 32);
    }
}

// ---------------- K3 (fused): chunk-offset scan + per-value prefixes -------
__global__ void k_fill() {
    int i = threadIdx.x;

    // scan the 256 chunk totals in-block; keep this block's exclusive offset
    long long cp   = pack2(d_chunkFlag[i], d_chunkTri[i]);
    long long cinc = block_scan_ll(cp);
    __shared__ long long s_blockOff;
    if (i == (int)blockIdx.x) s_blockOff = cinc - cp;
    if (blockIdx.x == 0 && i == NCHUNK - 1)
        d_triOffV[VMAX] = (int)(cinc & 0xffffffffLL);   // sentinel = T
    __syncthreads();   // s_blockOff visible; also isolates the two scans

    int v = blockIdx.x * CHUNK + i;
    int cnt = d_pos[v + 1] - d_pos[v];
    long long p = pack2(cnt > 0, cnt * (cnt - 1) / 2);
    long long excl = block_scan_ll(p) - p + s_blockOff;
    d_triOffV[v] = (int)(excl & 0xffffffffLL);
    d_segIdV[v]  = (int)(excl >> 32);
}

// full-range owner search: largest v in [0, VMAX-1] with triOffV[v] <= t
__device__ __forceinline__ int owner_full(int t) {
    int lo = 0, hi = VMAX - 1;
    #pragma unroll
    for (int step = 0; step < 16; step++) {
        int mid = (lo + hi + 1) >> 1;
        if (__ldg(&d_triOffV[mid]) <= t) lo = mid; else hi = mid - 1;
    }
    return lo;
}

// ---------------- K4: emit — coalesced mapping, coarse search --------------
// Thread tid handles t = blockStart + k*EMIT_BLOCK + tid: every warp store
// writes 32 consecutive floats (a full 128B line) in each planar stream.
__global__ void k_emit(float* __restrict__ out, int T) {
    __shared__ int s_vlo, s_vhi;
    int blockStart = blockIdx.x * TRIPLES_PER_BLOCK;
    int blockLast  = blockStart + TRIPLES_PER_BLOCK - 1;
    if (blockLast >= T) blockLast = T - 1;

    if (threadIdx.x == 0)  s_vlo = owner_full(blockStart);
    if (threadIdx.x == 32) s_vhi = owner_full(blockLast);
    __syncthreads();

    int t0 = blockStart + threadIdx.x;
    if (t0 >= T) return;

    // narrowed owner search for the first t
    int lo = s_vlo, hi = s_vhi;
    while (lo < hi) {
        int mid = (lo + hi + 1) >> 1;
        if (__ldg(&d_triOffV[mid]) <= t0) lo = mid; else hi = mid - 1;
    }
    int v       = lo;
    int off     = __ldg(&d_triOffV[v]);
    int nextOff = __ldg(&d_triOffV[v + 1]);
    int beg     = __ldg(&d_pos[v]);
    int c       = __ldg(&d_pos[v + 1]) - beg;
    float fs    = (float)__ldg(&d_segIdV[v]);
    int endR    = c * (c - 1) / 2 - 1;     // M - 1

    #pragma unroll
    for (int k = 0; k < EMIT_PER_THREAD; k++) {
        int t = t0 + k * EMIT_BLOCK;
        if (t >= T) break;
        while (t >= nextOff) {             // advance owner (skips empty values)
            v++;
            off = nextOff;
            nextOff = __ldg(&d_triOffV[v + 1]);
            beg = __ldg(&d_pos[v]);
            c   = __ldg(&d_pos[v + 1]) - beg;
            fs  = (float)__ldg(&d_segIdV[v]);
            endR = c * (c - 1) / 2 - 1;
        }
        int rr = endR - (t - off);
        int a_rev = (int)floorf((sqrtf(8.0f * (float)rr + 1.0f) - 1.0f) * 0.5f);
        if (a_rev < 0) a_rev = 0;
        if ((a_rev + 1) * (a_rev + 2) / 2 <= rr) a_rev++;
        if (a_rev * (a_rev + 1) / 2 > rr)        a_rev--;
        int a = c - 2 - a_rev;
        int b = c - 1 - (rr - a_rev * (a_rev + 1) / 2);

        out[t]         = fs;
        out[T + t]     = (float)(beg + a);
        out[2 * T + t] = (float)(beg + b);
    }
}

// ---------------------------------------------------------------------------
extern "C" void kernel_launch(void* const* d_in, const int* in_sizes, int n_in,
                              void* d_out, int out_size) {
    const int* idx = (const int*)d_in[0];
    int n = in_sizes[0];
    int T = out_size / 3;                 // planar [s | j | k], float32
    float* out = (float*)d_out;

    k_pos<<<(VMAX + 1 + 255) / 256, 256>>>(idx, n);
    k_sum<<<NCHUNK, CHUNK>>>();
    k_fill<<<NCHUNK, CHUNK>>>();
    int nblk = (T + TRIPLES_PER_BLOCK - 1) / TRIPLES_PER_BLOCK;
    k_emit<<<nblk, EMIT_BLOCK>>>(out, T);
}

// round 15
// speedup vs baseline: 3.8737x; 1.0346x over previous
#include <cuda_runtime.h>
#include <cstdint>

// ---------------------------------------------------------------------------
// CollectAtomTriples: idx_i SORTED int32 [n], values in [0, VMAX). For each
// run (segment) s of equal values (size c, start off) emit all C(c,2) pairs
// (a<b, combinations order), PLANAR FLOAT32 output (values < 2^24: exact):
//   out[0:T)=s   out[T:2T)=off+a   out[2T:3T)=off+b
// ---------------------------------------------------------------------------

#define VMAX   65536
#define NCHUNK 256
#define CHUNK  256              // VMAX / NCHUNK
#define EMIT_PER_THREAD 16
#define EMIT_BLOCK 256
#define TRIPLES_PER_BLOCK (EMIT_PER_THREAD * EMIT_BLOCK)   // 4096
#define TBL 4096                // triangular-decode table (covers c <= 91)

__device__ int d_pos[VMAX + 1];       // pos[v] = lower_bound(idx, v)
__device__ int d_triOffV[VMAX + 1];   // exclusive prefix of C(cnt(v),2); [VMAX]=T
__device__ int d_segIdV[VMAX];        // exclusive prefix of present-flag
__device__ int d_chunkTri[NCHUNK];
__device__ int d_chunkFlag[NCHUNK];
__device__ int d_triTbl[TBL];         // packed (a_rev<<16)|rem for each rr

// ---------------- exact sqrt-based decode (used for table + fallback) ------
__device__ __forceinline__ int tri_decode_packed(int rr) {
    int a_rev = (int)floorf((sqrtf(8.0f * (float)rr + 1.0f) - 1.0f) * 0.5f);
    if (a_rev < 0) a_rev = 0;
    if ((a_rev + 1) * (a_rev + 2) / 2 <= rr) a_rev++;
    if (a_rev * (a_rev + 1) / 2 > rr)        a_rev--;
    int rem = rr - a_rev * (a_rev + 1) / 2;
    return (a_rev << 16) | rem;
}

// ---------------- K0: fill the decode table --------------------------------
__global__ void k_tbl() {
    int rr = blockIdx.x * blockDim.x + threadIdx.x;
    if (rr < TBL) d_triTbl[rr] = tri_decode_packed(rr);
}

// ---------------- K1a: boundary values of pos ------------------------------
__global__ void k_pos_bounds(const int* __restrict__ idx, int n) {
    int v = blockIdx.x * blockDim.x + threadIdx.x;
    if (v > VMAX) return;
    int first = __ldg(&idx[0]);
    int last  = __ldg(&idx[n - 1]);
    if (v <= first)    d_pos[v] = 0;
    else if (v > last) d_pos[v] = n;
}

// ---------------- K1b: scatter pos at value changes ------------------------
__global__ void k_pos_scatter(const int* __restrict__ idx, int n) {
    int p = blockIdx.x * blockDim.x + threadIdx.x;
    if (p == 0 || p >= n) return;
    int a = __ldg(&idx[p - 1]);
    int b = __ldg(&idx[p]);
    for (int v = a + 1; v <= b; v++) d_pos[v] = p;   // gaps are tiny here
}

__device__ __forceinline__ long long pack2(int fl, int tri) {
    return ((long long)fl << 32) | (unsigned int)tri;
}

// block-wide inclusive scan of packed 64-bit values (blockDim.x = 256)
__device__ __forceinline__ long long block_scan_ll(long long v) {
    const int lane = threadIdx.x & 31;
    const int warp = threadIdx.x >> 5;
    #pragma unroll
    for (int o = 1; o < 32; o <<= 1) {
        long long u = __shfl_up_sync(0xffffffffu, v, o);
        if (lane >= o) v += u;
    }
    __shared__ long long wsum[8];
    if (lane == 31) wsum[warp] = v;
    __syncthreads();
    if (warp == 0) {
        long long w = (lane < 8) ? wsum[lane] : 0;
        #pragma unroll
        for (int o = 1; o < 8; o <<= 1) {
            long long u = __shfl_up_sync(0xffffffffu, w, o);
            if (lane >= o) w += u;
        }
        if (lane < 8) wsum[lane] = w;
    }
    __syncthreads();
    long long add = (warp > 0) ? wsum[warp - 1] : 0;
    return v + add;
}

// ---------------- K2: per-chunk totals -------------------------------------
__global__ void k_sum() {
    int v = blockIdx.x * CHUNK + threadIdx.x;
    int cnt = d_pos[v + 1] - d_pos[v];
    long long p = pack2(cnt > 0, cnt * (cnt - 1) / 2);
    const int lane = threadIdx.x & 31;
    const int warp = threadIdx.x >> 5;
    #pragma unroll
    for (int o = 16; o > 0; o >>= 1)
        p += __shfl_down_sync(0xffffffffu, p, o);
    __shared__ long long ws[8];
    if (lane == 0) ws[warp] = p;
    __syncthreads();
    if (threadIdx.x == 0) {
        long long s = 0;
        #pragma unroll
        for (int w = 0; w < 8; w++) s += ws[w];
        d_chunkTri[blockIdx.x]  = (int)(s & 0xffffffffLL);
        d_chunkFlag[blockIdx.x] = (int)(s >> 32);
    }
}

// ---------------- K3 (fused): chunk-offset scan + per-value prefixes -------
__global__ void k_fill() {
    int i = threadIdx.x;
    long long cp   = pack2(d_chunkFlag[i], d_chunkTri[i]);
    long long cinc = block_scan_ll(cp);
    __shared__ long long s_blockOff;
    if (i == (int)blockIdx.x) s_blockOff = cinc - cp;
    if (blockIdx.x == 0 && i == NCHUNK - 1)
        d_triOffV[VMAX] = (int)(cinc & 0xffffffffLL);   // sentinel = T
    __syncthreads();

    int v = blockIdx.x * CHUNK + i;
    int cnt = d_pos[v + 1] - d_pos[v];
    long long p = pack2(cnt > 0, cnt * (cnt - 1) / 2);
    long long excl = block_scan_ll(p) - p + s_blockOff;
    d_triOffV[v] = (int)(excl & 0xffffffffLL);
    d_segIdV[v]  = (int)(excl >> 32);
}

// full-range owner search: largest v in [0, VMAX-1] with triOffV[v] <= t
__device__ __forceinline__ int owner_full(int t) {
    int lo = 0, hi = VMAX - 1;
    #pragma unroll
    for (int step = 0; step < 16; step++) {
        int mid = (lo + hi + 1) >> 1;
        if (__ldg(&d_triOffV[mid]) <= t) lo = mid; else hi = mid - 1;
    }
    return lo;
}

// ---------------- K4: emit — coalesced mapping, smem decode table ----------
__global__ void k_emit(float* __restrict__ out, int T) {
    __shared__ int s_tbl[TBL];
    __shared__ int s_vlo, s_vhi;

    int blockStart = blockIdx.x * TRIPLES_PER_BLOCK;
    int blockLast  = blockStart + TRIPLES_PER_BLOCK - 1;
    if (blockLast >= T) blockLast = T - 1;

    if (threadIdx.x == 0)  s_vlo = owner_full(blockStart);
    if (threadIdx.x == 32) s_vhi = owner_full(blockLast);
    #pragma unroll
    for (int i = 0; i < TBL / EMIT_BLOCK; i++)
        s_tbl[i * EMIT_BLOCK + threadIdx.x] = d_triTbl[i * EMIT_BLOCK + threadIdx.x];
    __syncthreads();

    int t0 = blockStart + threadIdx.x;
    if (t0 >= T) return;

    int lo = s_vlo, hi = s_vhi;
    while (lo < hi) {
        int mid = (lo + hi + 1) >> 1;
        if (__ldg(&d_triOffV[mid]) <= t0) lo = mid; else hi = mid - 1;
    }
    int v       = lo;
    int off     = __ldg(&d_triOffV[v]);
    int nextOff = __ldg(&d_triOffV[v + 1]);
    int beg     = __ldg(&d_pos[v]);
    int c       = __ldg(&d_pos[v + 1]) - beg;
    float fs    = (float)__ldg(&d_segIdV[v]);
    int endR    = c * (c - 1) / 2 - 1;     // M - 1

    #pragma unroll
    for (int k = 0; k < EMIT_PER_THREAD; k++) {
        int t = t0 + k * EMIT_BLOCK;
        if (t >= T) break;
        while (t >= nextOff) {             // advance owner (skips empty values)
            v++;
            off = nextOff;
            nextOff = __ldg(&d_triOffV[v + 1]);
            beg = __ldg(&d_pos[v]);
            c   = __ldg(&d_pos[v + 1]) - beg;
            fs  = (float)__ldg(&d_segIdV[v]);
            endR = c * (c - 1) / 2 - 1;
        }
        int rr = endR - (t - off);
        int pk = (rr < TBL) ? s_tbl[rr] : tri_decode_packed(rr);
        int a = c - 2 - (pk >> 16);
        int b = c - 1 - (pk & 0xffff);

        out[t]         = fs;
        out[T + t]     = (float)(beg + a);
        out[2 * T + t] = (float)(beg + b);
    }
}

// ---------------------------------------------------------------------------
extern "C" void kernel_launch(void* const* d_in, const int* in_sizes, int n_in,
                              void* d_out, int out_size) {
    const int* idx = (const int*)d_in[0];
    int n = in_sizes[0];
    int T = out_size / 3;                 // planar [s | j | k], float32
    float* out = (float*)d_out;

    k_tbl<<<TBL / 256, 256>>>();
    k_pos_bounds<<<(VMAX + 1 + 255) / 256, 256>>>(idx, n);
    k_pos_scatter<<<(n + 255) / 256, 256>>>(idx, n);
    k_sum<<<NCHUNK, CHUNK>>>();
    k_fill<<<NCHUNK, CHUNK>>>();
    int nblk = (T + TRIPLES_PER_BLOCK - 1) / TRIPLES_PER_BLOCK;
    k_emit<<<nblk, EMIT_BLOCK>>>(out, T);
}

// round 16
// speedup vs baseline: 3.9984x; 1.0322x over previous
#include <cuda_runtime.h>
#include <cstdint>

// ---------------------------------------------------------------------------
// CollectAtomTriples: idx_i SORTED int32 [n], values in [0, VMAX). For each
// run (segment) s of equal values (size c, start off) emit all C(c,2) pairs
// (a<b, combinations order), PLANAR FLOAT32 output (values < 2^24: exact):
//   out[0:T)=s   out[T:2T)=off+a   out[2T:3T)=off+b
// ---------------------------------------------------------------------------

#define VMAX   65536
#define NCHUNK 256
#define CHUNK  256              // VMAX / NCHUNK
#define EMIT_PER_THREAD 16
#define EMIT_BLOCK 256
#define TRIPLES_PER_BLOCK (EMIT_PER_THREAD * EMIT_BLOCK)   // 4096
#define TBL 4096                // decode table (covers c <= 91)

__device__ int    d_pos[VMAX + 1];     // pos[v] = lower_bound(idx, v)
__device__ int    d_triOffV[VMAX + 1]; // exclusive prefix of C(cnt(v),2); [VMAX]=T
__device__ int    d_segIdV[VMAX];      // exclusive prefix of present-flag
__device__ int    d_chunkTri[NCHUNK];
__device__ int    d_chunkFlag[NCHUNK];
__device__ float2 d_triTblF[TBL];      // (float a_rev, float rem) per rr

// ---------------- exact sqrt-based decode (table init + fallback) ----------
__device__ __forceinline__ void tri_decode(int rr, int& a_rev, int& rem) {
    a_rev = (int)floorf((sqrtf(8.0f * (float)rr + 1.0f) - 1.0f) * 0.5f);
    if (a_rev < 0) a_rev = 0;
    if ((a_rev + 1) * (a_rev + 2) / 2 <= rr) a_rev++;
    if (a_rev * (a_rev + 1) / 2 > rr)        a_rev--;
    rem = rr - a_rev * (a_rev + 1) / 2;
}

// ---------------- K0: fill the decode table --------------------------------
__global__ void k_tbl() {
    int rr = blockIdx.x * blockDim.x + threadIdx.x;
    if (rr < TBL) {
        int ar, rem;
        tri_decode(rr, ar, rem);
        d_triTblF[rr] = make_float2((float)ar, (float)rem);
    }
}

// ---------------- K1a: boundary values of pos ------------------------------
__global__ void k_pos_bounds(const int* __restrict__ idx, int n) {
    int v = blockIdx.x * blockDim.x + threadIdx.x;
    if (v > VMAX) return;
    int first = __ldg(&idx[0]);
    int last  = __ldg(&idx[n - 1]);
    if (v <= first)    d_pos[v] = 0;
    else if (v > last) d_pos[v] = n;
}

// ---------------- K1b: scatter pos at value changes ------------------------
__global__ void k_pos_scatter(const int* __restrict__ idx, int n) {
    int p = blockIdx.x * blockDim.x + threadIdx.x;
    if (p == 0 || p >= n) return;
    int a = __ldg(&idx[p - 1]);
    int b = __ldg(&idx[p]);
    for (int v = a + 1; v <= b; v++) d_pos[v] = p;   // gaps are tiny here
}

__device__ __forceinline__ long long pack2(int fl, int tri) {
    return ((long long)fl << 32) | (unsigned int)tri;
}

// block-wide inclusive scan of packed 64-bit values (blockDim.x = 256)
__device__ __forceinline__ long long block_scan_ll(long long v) {
    const int lane = threadIdx.x & 31;
    const int warp = threadIdx.x >> 5;
    #pragma unroll
    for (int o = 1; o < 32; o <<= 1) {
        long long u = __shfl_up_sync(0xffffffffu, v, o);
        if (lane >= o) v += u;
    }
    __shared__ long long wsum[8];
    if (lane == 31) wsum[warp] = v;
    __syncthreads();
    if (warp == 0) {
        long long w = (lane < 8) ? wsum[lane] : 0;
        #pragma unroll
        for (int o = 1; o < 8; o <<= 1) {
            long long u = __shfl_up_sync(0xffffffffu, w, o);
            if (lane >= o) w += u;
        }
        if (lane < 8) wsum[lane] = w;
    }
    __syncthreads();
    long long add = (warp > 0) ? wsum[warp - 1] : 0;
    return v + add;
}

// ---------------- K2: per-chunk totals -------------------------------------
__global__ void k_sum() {
    int v = blockIdx.x * CHUNK + threadIdx.x;
    int cnt = d_pos[v + 1] - d_pos[v];
    long long p = pack2(cnt > 0, cnt * (cnt - 1) / 2);
    const int lane = threadIdx.x & 31;
    const int warp = threadIdx.x >> 5;
    #pragma unroll
    for (int o = 16; o > 0; o >>= 1)
        p += __shfl_down_sync(0xffffffffu, p, o);
    __shared__ long long ws[8];
    if (lane == 0) ws[warp] = p;
    __syncthreads();
    if (threadIdx.x == 0) {
        long long s = 0;
        #pragma unroll
        for (int w = 0; w < 8; w++) s += ws[w];
        d_chunkTri[blockIdx.x]  = (int)(s & 0xffffffffLL);
        d_chunkFlag[blockIdx.x] = (int)(s >> 32);
    }
}

// ---------------- K3 (fused): chunk-offset scan + per-value prefixes -------
__global__ void k_fill() {
    int i = threadIdx.x;
    long long cp   = pack2(d_chunkFlag[i], d_chunkTri[i]);
    long long cinc = block_scan_ll(cp);
    __shared__ long long s_blockOff;
    if (i == (int)blockIdx.x) s_blockOff = cinc - cp;
    if (blockIdx.x == 0 && i == NCHUNK - 1)
        d_triOffV[VMAX] = (int)(cinc & 0xffffffffLL);   // sentinel = T
    __syncthreads();

    int v = blockIdx.x * CHUNK + i;
    int cnt = d_pos[v + 1] - d_pos[v];
    long long p = pack2(cnt > 0, cnt * (cnt - 1) / 2);
    long long excl = block_scan_ll(p) - p + s_blockOff;
    d_triOffV[v] = (int)(excl & 0xffffffffLL);
    d_segIdV[v]  = (int)(excl >> 32);
}

// full-range owner search: largest v in [0, VMAX-1] with triOffV[v] <= t
__device__ __forceinline__ int owner_full(int t) {
    int lo = 0, hi = VMAX - 1;
    #pragma unroll
    for (int step = 0; step < 16; step++) {
        int mid = (lo + hi + 1) >> 1;
        if (__ldg(&d_triOffV[mid]) <= t) lo = mid; else hi = mid - 1;
    }
    return lo;
}

// ---------------- K4: emit ---------------------------------------------------
// Thread tid handles t = blockStart + k*EMIT_BLOCK + tid (full-line coalesced
// warp stores). Per-segment state hoisted; per-triple work: rr = rrBase - t,
// LDG.64 table (L1-resident), 2 FADD, 3 STG.
struct SegState {
    int v, nextOff, rrBase;          // rrBase = endR + off
    float fs, fj, fk;                // s, float(beg+c-2), float(beg+c-1)
};

__device__ __forceinline__ void seg_load(SegState& st) {
    int off  = __ldg(&d_triOffV[st.v]);
    st.nextOff = __ldg(&d_triOffV[st.v + 1]);
    int beg  = __ldg(&d_pos[st.v]);
    int c    = __ldg(&d_pos[st.v + 1]) - beg;
    st.fs    = (float)__ldg(&d_segIdV[st.v]);
    st.rrBase = c * (c - 1) / 2 - 1 + off;
    st.fj    = (float)(beg + c - 2);
    st.fk    = (float)(beg + c - 1);
}

__device__ __forceinline__ void emit_one(float* __restrict__ out, int T, int t,
                                         SegState& st) {
    while (t >= st.nextOff) { st.v++; seg_load(st); }
    int rr = st.rrBase - t;
    float2 ab;
    if (rr < TBL) {
        ab = __ldg(&d_triTblF[rr]);
    } else {                                  // never taken for c <= 91
        int ar, rem; tri_decode(rr, ar, rem);
        ab = make_float2((float)ar, (float)rem);
    }
    out[t]         = st.fs;
    out[T + t]     = st.fj - ab.x;
    out[2 * T + t] = st.fk - ab.y;
}

__global__ void k_emit(float* __restrict__ out, int T) {
    __shared__ int s_vlo, s_vhi;
    int blockStart = blockIdx.x * TRIPLES_PER_BLOCK;
    int blockLast  = blockStart + TRIPLES_PER_BLOCK - 1;
    bool full = (blockLast < T);
    if (!full) blockLast = T - 1;

    if (threadIdx.x == 0)  s_vlo = owner_full(blockStart);
    if (threadIdx.x == 32) s_vhi = owner_full(blockLast);
    __syncthreads();

    int t0 = blockStart + threadIdx.x;
    if (t0 >= T) return;

    int lo = s_vlo, hi = s_vhi;
    while (lo < hi) {
        int mid = (lo + hi + 1) >> 1;
        if (__ldg(&d_triOffV[mid]) <= t0) lo = mid; else hi = mid - 1;
    }
    SegState st;
    st.v = lo;
    seg_load(st);

    if (full) {
        #pragma unroll
        for (int k = 0; k < EMIT_PER_THREAD; k++)
            emit_one(out, T, t0 + k * EMIT_BLOCK, st);
    } else {
        #pragma unroll
        for (int k = 0; k < EMIT_PER_THREAD; k++) {
            int t = t0 + k * EMIT_BLOCK;
            if (t >= T) break;
            emit_one(out, T, t, st);
        }
    }
}

// ---------------------------------------------------------------------------
extern "C" void kernel_launch(void* const* d_in, const int* in_sizes, int n_in,
                              void* d_out, int out_size) {
    const int* idx = (const int*)d_in[0];
    int n = in_sizes[0];
    int T = out_size / 3;                 // planar [s | j | k], float32
    float* out = (float*)d_out;

    k_tbl<<<TBL / 256, 256>>>();
    k_pos_bounds<<<(VMAX + 1 + 255) / 256, 256>>>(idx, n);
    k_pos_scatter<<<(n + 255) / 256, 256>>>(idx, n);
    k_sum<<<NCHUNK, CHUNK>>>();
    k_fill<<<NCHUNK, CHUNK>>>();
    int nblk = (T + TRIPLES_PER_BLOCK - 1) / TRIPLES_PER_BLOCK;
    k_emit<<<nblk, EMIT_BLOCK>>>(out, T);
}

// round 17
// speedup vs baseline: 4.3514x; 1.0883x over previous
#include <cuda_runtime.h>
#include <cstdint>

// ---------------------------------------------------------------------------
// CollectAtomTriples: idx_i SORTED int32 [n], values in [0, VMAX). For each
// run (segment) s of equal values (size c, start off) emit all C(c,2) pairs
// (a<b, combinations order), PLANAR FLOAT32 output (values < 2^24: exact):
//   out[0:T)=s   out[T:2T)=off+a   out[2T:3T)=off+b
// ---------------------------------------------------------------------------

#define VMAX   65536
#define NCHUNK 256
#define CHUNK  256              // VMAX / NCHUNK
#define EMIT_PER_THREAD 32
#define EMIT_BLOCK 256
#define TRIPLES_PER_BLOCK (EMIT_PER_THREAD * EMIT_BLOCK)   // 8192
#define TBL 4096                // decode table (covers c <= 91)

__device__ int    d_pos[VMAX + 1];     // pos[v] = lower_bound(idx, v)
__device__ int    d_triOffV[VMAX + 1]; // exclusive prefix of C(cnt(v),2); [VMAX]=T
__device__ int    d_segIdV[VMAX];      // exclusive prefix of present-flag
__device__ int    d_chunkTri[NCHUNK];
__device__ int    d_chunkFlag[NCHUNK];
__device__ float2 d_triTblF[TBL];      // (float a_rev, float rem) per rr

// ---------------- exact sqrt-based decode (table init + fallback) ----------
__device__ __forceinline__ void tri_decode(int rr, int& a_rev, int& rem) {
    a_rev = (int)floorf((sqrtf(8.0f * (float)rr + 1.0f) - 1.0f) * 0.5f);
    if (a_rev < 0) a_rev = 0;
    if ((a_rev + 1) * (a_rev + 2) / 2 <= rr) a_rev++;
    if (a_rev * (a_rev + 1) / 2 > rr)        a_rev--;
    rem = rr - a_rev * (a_rev + 1) / 2;
}

// ---------------- K1 (fused init): table + pos bounds + pos scatter --------
__global__ void k_init(const int* __restrict__ idx, int n) {
    int p = blockIdx.x * blockDim.x + threadIdx.x;

    // decode table (first 4096 threads)
    if (p < TBL) {
        int ar, rem;
        tri_decode(p, ar, rem);
        d_triTblF[p] = make_float2((float)ar, (float)rem);
    }

    // pos boundary values (first VMAX+1 threads)
    if (p <= VMAX) {
        int first = __ldg(&idx[0]);
        int last  = __ldg(&idx[n - 1]);
        if (p <= first)    d_pos[p] = 0;
        else if (p > last) d_pos[p] = n;
    }

    // pos scatter at value changes (threads 1..n-1)
    if (p >= 1 && p < n) {
        int a = __ldg(&idx[p - 1]);
        int b = __ldg(&idx[p]);
        for (int v = a + 1; v <= b; v++) d_pos[v] = p;   // gaps are tiny here
    }
}

__device__ __forceinline__ long long pack2(int fl, int tri) {
    return ((long long)fl << 32) | (unsigned int)tri;
}

// block-wide inclusive scan of packed 64-bit values (blockDim.x = 256)
__device__ __forceinline__ long long block_scan_ll(long long v) {
    const int lane = threadIdx.x & 31;
    const int warp = threadIdx.x >> 5;
    #pragma unroll
    for (int o = 1; o < 32; o <<= 1) {
        long long u = __shfl_up_sync(0xffffffffu, v, o);
        if (lane >= o) v += u;
    }
    __shared__ long long wsum[8];
    if (lane == 31) wsum[warp] = v;
    __syncthreads();
    if (warp == 0) {
        long long w = (lane < 8) ? wsum[lane] : 0;
        #pragma unroll
        for (int o = 1; o < 8; o <<= 1) {
            long long u = __shfl_up_sync(0xffffffffu, w, o);
            if (lane >= o) w += u;
        }
        if (lane < 8) wsum[lane] = w;
    }
    __syncthreads();
    long long add = (warp > 0) ? wsum[warp - 1] : 0;
    return v + add;
}

// ---------------- K2: per-chunk totals -------------------------------------
__global__ void k_sum() {
    int v = blockIdx.x * CHUNK + threadIdx.x;
    int cnt = d_pos[v + 1] - d_pos[v];
    long long p = pack2(cnt > 0, cnt * (cnt - 1) / 2);
    const int lane = threadIdx.x & 31;
    const int warp = threadIdx.x >> 5;
    #pragma unroll
    for (int o = 16; o > 0; o >>= 1)
        p += __shfl_down_sync(0xffffffffu, p, o);
    __shared__ long long ws[8];
    if (lane == 0) ws[warp] = p;
    __syncthreads();
    if (threadIdx.x == 0) {
        long long s = 0;
        #pragma unroll
        for (int w = 0; w < 8; w++) s += ws[w];
        d_chunkTri[blockIdx.x]  = (int)(s & 0xffffffffLL);
        d_chunkFlag[blockIdx.x] = (int)(s >> 32);
    }
}

// ---------------- K3 (fused): chunk-offset scan + per-value prefixes -------
__global__ void k_fill() {
    int i = threadIdx.x;
    long long cp   = pack2(d_chunkFlag[i], d_chunkTri[i]);
    long long cinc = block_scan_ll(cp);
    __shared__ long long s_blockOff;
    if (i == (int)blockIdx.x) s_blockOff = cinc - cp;
    if (blockIdx.x == 0 && i == NCHUNK - 1)
        d_triOffV[VMAX] = (int)(cinc & 0xffffffffLL);   // sentinel = T
    __syncthreads();

    int v = blockIdx.x * CHUNK + i;
    int cnt = d_pos[v + 1] - d_pos[v];
    long long p = pack2(cnt > 0, cnt * (cnt - 1) / 2);
    long long excl = block_scan_ll(p) - p + s_blockOff;
    d_triOffV[v] = (int)(excl & 0xffffffffLL);
    d_segIdV[v]  = (int)(excl >> 32);
}

// full-range owner search: largest v in [0, VMAX-1] with triOffV[v] <= t
__device__ __forceinline__ int owner_full(int t) {
    int lo = 0, hi = VMAX - 1;
    #pragma unroll
    for (int step = 0; step < 16; step++) {
        int mid = (lo + hi + 1) >> 1;
        if (__ldg(&d_triOffV[mid]) <= t) lo = mid; else hi = mid - 1;
    }
    return lo;
}

// ---------------- K4: emit ---------------------------------------------------
struct SegState {
    int v, nextOff, rrBase;          // rrBase = endR + off
    float fs, fj, fk;                // s, float(beg+c-2), float(beg+c-1)
};

__device__ __forceinline__ void seg_load(SegState& st) {
    int off  = __ldg(&d_triOffV[st.v]);
    st.nextOff = __ldg(&d_triOffV[st.v + 1]);
    int beg  = __ldg(&d_pos[st.v]);
    int c    = __ldg(&d_pos[st.v + 1]) - beg;
    st.fs    = (float)__ldg(&d_segIdV[st.v]);
    st.rrBase = c * (c - 1) / 2 - 1 + off;
    st.fj    = (float)(beg + c - 2);
    st.fk    = (float)(beg + c - 1);
}

__device__ __forceinline__ void emit_one(float* __restrict__ out, int T, int t,
                                         SegState& st) {
    while (t >= st.nextOff) { st.v++; seg_load(st); }
    int rr = st.rrBase - t;
    float2 ab;
    if (rr < TBL) {
        ab = __ldg(&d_triTblF[rr]);
    } else {                                  // never taken for c <= 91
        int ar, rem; tri_decode(rr, ar, rem);
        ab = make_float2((float)ar, (float)rem);
    }
    out[t]         = st.fs;
    out[T + t]     = st.fj - ab.x;
    out[2 * T + t] = st.fk - ab.y;
}

__global__ void k_emit(float* __restrict__ out, int T) {
    __shared__ int s_vlo, s_vhi;
    int blockStart = blockIdx.x * TRIPLES_PER_BLOCK;
    int blockLast  = blockStart + TRIPLES_PER_BLOCK - 1;
    bool full = (blockLast < T);
    if (!full) blockLast = T - 1;

    if (threadIdx.x == 0)  s_vlo = owner_full(blockStart);
    if (threadIdx.x == 32) s_vhi = owner_full(blockLast);
    __syncthreads();

    int t0 = blockStart + threadIdx.x;
    if (t0 >= T) return;

    int lo = s_vlo, hi = s_vhi;
    while (lo < hi) {
        int mid = (lo + hi + 1) >> 1;
        if (__ldg(&d_triOffV[mid]) <= t0) lo = mid; else hi = mid - 1;
    }
    SegState st;
    st.v = lo;
    seg_load(st);

    if (full) {
        #pragma unroll
        for (int k = 0; k < EMIT_PER_THREAD; k++)
            emit_one(out, T, t0 + k * EMIT_BLOCK, st);
    } else {
        #pragma unroll
        for (int k = 0; k < EMIT_PER_THREAD; k++) {
            int t = t0 + k * EMIT_BLOCK;
            if (t >= T) break;
            emit_one(out, T, t, st);
        }
    }
}

// ---------------------------------------------------------------------------
extern "C" void kernel_launch(void* const* d_in, const int* in_sizes, int n_in,
                              void* d_out, int out_size) {
    const int* idx = (const int*)d_in[0];
    int n = in_sizes[0];
    int T = out_size / 3;                 // planar [s | j | k], float32
    float* out = (float*)d_out;

    int initThreads = (n > VMAX + 1) ? n : (VMAX + 1);
    k_init<<<(initThreads + 255) / 256, 256>>>(idx, n);
    k_sum<<<NCHUNK, CHUNK>>>();
    k_fill<<<NCHUNK, CHUNK>>>();
    int nblk = (T + TRIPLES_PER_BLOCK - 1) / TRIPLES_PER_BLOCK;
    k_emit<<<nblk, EMIT_BLOCK>>>(out, T);
}